// round 7
// baseline (speedup 1.0000x reference)
#include <cuda_runtime.h>
#include <cstdint>

// Problem constants (fixed by the reference setup)
#define PB 16
#define PL 4096
#define PD 768
#define PS 128
#define D4 (PD / 4)          // 192 float4 per row
#define NTHREADS D4          // one float4 per thread
#define NBLOCKS (PB * PS)    // one block per (batch, segment)

__global__ __launch_bounds__(NTHREADS)
void pooling_kernel(const float* __restrict__ wv,
                    const int*   __restrict__ rep_ids,
                    const int*   __restrict__ rep_mask,
                    const int*   __restrict__ lengths,
                    const int*   __restrict__ len_mask,
                    float* __restrict__ out,
                    long long out_size)
{
    const int blk = blockIdx.x;
    const int b = blk >> 7;          // / PS
    const int s = blk & (PS - 1);    // % PS
    const int t = threadIdx.x;

    __shared__ int sh_start;
    __shared__ int sh_len;
    __shared__ int sh_cnt[NTHREADS / 32];

    if (t == 0) {
        const int* lp = lengths + b * PS;
        int acc = 0;
        #pragma unroll 8
        for (int i = 0; i < s; ++i) acc += lp[i];
        sh_start = acc;
        sh_len   = lp[s];
    }
    __syncthreads();
    const int start = sh_start;
    const int len   = sh_len;

    const float4* __restrict__ wv4 = reinterpret_cast<const float4*>(wv);

    // ---- segment mean path: sum + per-feature nonzero count ----
    float4 sum = make_float4(0.f, 0.f, 0.f, 0.f);
    int cx = 0, cy = 0, cz = 0, cw = 0;

    long long base = ((long long)b * PL + start) * D4 + t;
    #pragma unroll 8
    for (int k = 0; k < len; ++k) {
        float4 v = __ldg(&wv4[base + (long long)k * D4]);
        sum.x += v.x; sum.y += v.y; sum.z += v.z; sum.w += v.w;
        cx += (v.x != 0.f); cy += (v.y != 0.f);
        cz += (v.z != 0.f); cw += (v.w != 0.f);
    }

    // total nonzero count across all 768 features of this segment
    int my_cnt = cx + cy + cz + cw;
    #pragma unroll
    for (int o = 16; o > 0; o >>= 1)
        my_cnt += __shfl_down_sync(0xffffffffu, my_cnt, o);
    if ((t & 31) == 0) sh_cnt[t >> 5] = my_cnt;
    __syncthreads();
    int total_nz = 0;
    #pragma unroll
    for (int w = 0; w < NTHREADS / 32; ++w) total_nz += sh_cnt[w];

    const float lm = len_mask[b * PS + s] ? 1.f : 0.f;

    float4 mv;
    if (total_nz == 0) {
        // fallback: word_vectors[0, 0, :]
        mv = __ldg(&wv4[t]);
    } else {
        mv.x = sum.x / fmaxf((float)cx, 1.f);
        mv.y = sum.y / fmaxf((float)cy, 1.f);
        mv.z = sum.z / fmaxf((float)cz, 1.f);
        mv.w = sum.w / fmaxf((float)cw, 1.f);
    }
    mv.x *= lm; mv.y *= lm; mv.z *= lm; mv.w *= lm;

    float4* __restrict__ out4 = reinterpret_cast<float4*>(out);
    // mean vectors go to the second half: out[b, S + s, :]
    out4[((long long)b * (2 * PS) + PS + s) * D4 + t] = mv;

    // ---- gather path: out[b, s, :] = wv[b, rep_ids[b,s], :] * rep_mask ----
    const int id = rep_ids[b * PS + s];
    const float rm = rep_mask[b * PS + s] ? 1.f : 0.f;
    float4 g = __ldg(&wv4[((long long)b * PL + id) * D4 + t]);
    g.x *= rm; g.y *= rm; g.z *= rm; g.w *= rm;
    out4[((long long)b * (2 * PS) + s) * D4 + t] = g;

    // ---- optional mask tail (if harness flattens the tuple's second output) ----
    const long long n_vec = (long long)PB * 2 * PS * PD;
    if (out_size > n_vec && t == 0) {
        long long mbase = n_vec + (long long)b * (2 * PS);
        if (mbase + s < out_size)       out[mbase + s]       = rm;
        if (mbase + PS + s < out_size)  out[mbase + PS + s]  = lm;
    }
}

extern "C" void kernel_launch(void* const* d_in, const int* in_sizes, int n_in,
                              void* d_out, int out_size) {
    const float* wv       = (const float*)d_in[0];
    const int*   rep_ids  = (const int*)d_in[1];
    const int*   rep_mask = (const int*)d_in[2];
    const int*   lengths  = (const int*)d_in[3];
    const int*   len_mask = (const int*)d_in[4];
    float* out = (float*)d_out;

    pooling_kernel<<<NBLOCKS, NTHREADS>>>(wv, rep_ids, rep_mask, lengths,
                                          len_mask, out, (long long)out_size);
}

// round 16
// speedup vs baseline: 1.0746x; 1.0746x over previous
#include <cuda_runtime.h>
#include <cstdint>

// Problem constants (fixed by the reference setup)
#define PB 16
#define PL 4096
#define PD 768
#define PS 128
#define D4 (PD / 4)          // 192 float4 per row
#define NTHREADS D4          // one float4 per thread
#define NBLOCKS (PB * PS)    // one block per (batch, segment)

__global__ __launch_bounds__(NTHREADS, 8)
void pooling_kernel(const float* __restrict__ wv,
                    const int*   __restrict__ rep_ids,
                    const int*   __restrict__ rep_mask,
                    const int*   __restrict__ lengths,
                    const int*   __restrict__ len_mask,
                    float* __restrict__ out,
                    long long out_size)
{
    const int blk = blockIdx.x;
    const int b = blk >> 7;          // / PS
    const int s = blk & (PS - 1);    // % PS
    const int t = threadIdx.x;

    __shared__ int sh_pref[NTHREADS / 32];   // prefix partials
    __shared__ int sh_cnt[NTHREADS / 32];    // nonzero-count partials
    __shared__ int sh_start;
    __shared__ int sh_len;

    // ---- parallel prefix: start = sum(lengths[b, 0:s]), len = lengths[b, s] ----
    {
        const int* lp = lengths + b * PS;
        int myl = (t < PS) ? lp[t] : 0;
        if (t == s) sh_len = myl;
        int contrib = (t < s) ? myl : 0;
        #pragma unroll
        for (int o = 16; o > 0; o >>= 1)
            contrib += __shfl_down_sync(0xffffffffu, contrib, o);
        if ((t & 31) == 0) sh_pref[t >> 5] = contrib;
        __syncthreads();
        if (t == 0) {
            int acc = 0;
            #pragma unroll
            for (int w = 0; w < NTHREADS / 32; ++w) acc += sh_pref[w];
            sh_start = acc;
        }
        __syncthreads();
    }
    const int start = sh_start;
    const int len   = sh_len;

    const float4* __restrict__ wv4 = reinterpret_cast<const float4*>(wv);

    // ---- segment mean path: sum + per-feature nonzero count ----
    float4 sum = make_float4(0.f, 0.f, 0.f, 0.f);
    int cx = 0, cy = 0, cz = 0, cw = 0;

    long long base = ((long long)b * PL + start) * D4 + t;
    #pragma unroll 8
    for (int k = 0; k < len; ++k) {
        float4 v = __ldcs(&wv4[base + (long long)k * D4]);   // evict-first stream
        sum.x += v.x; sum.y += v.y; sum.z += v.z; sum.w += v.w;
        cx += (v.x != 0.f); cy += (v.y != 0.f);
        cz += (v.z != 0.f); cw += (v.w != 0.f);
    }

    // ---- gather load issued early so its DRAM latency overlaps the reduce/divide tail ----
    const int id = rep_ids[b * PS + s];
    const float rm = rep_mask[b * PS + s] ? 1.f : 0.f;
    float4 g = __ldg(&wv4[((long long)b * PL + id) * D4 + t]);

    // total nonzero count across all 768 features of this segment
    int my_cnt = cx + cy + cz + cw;
    #pragma unroll
    for (int o = 16; o > 0; o >>= 1)
        my_cnt += __shfl_down_sync(0xffffffffu, my_cnt, o);
    if ((t & 31) == 0) sh_cnt[t >> 5] = my_cnt;
    __syncthreads();
    int total_nz = 0;
    #pragma unroll
    for (int w = 0; w < NTHREADS / 32; ++w) total_nz += sh_cnt[w];

    const float lm = len_mask[b * PS + s] ? 1.f : 0.f;

    float4 mv;
    if (total_nz == 0) {
        // fallback: word_vectors[0, 0, :]
        mv = __ldg(&wv4[t]);
    } else {
        mv.x = sum.x / fmaxf((float)cx, 1.f);
        mv.y = sum.y / fmaxf((float)cy, 1.f);
        mv.z = sum.z / fmaxf((float)cz, 1.f);
        mv.w = sum.w / fmaxf((float)cw, 1.f);
    }
    mv.x *= lm; mv.y *= lm; mv.z *= lm; mv.w *= lm;

    float4* __restrict__ out4 = reinterpret_cast<float4*>(out);
    // mean vectors go to the second half: out[b, S + s, :]
    __stcs(&out4[((long long)b * (2 * PS) + PS + s) * D4 + t], mv);

    // ---- gather path: out[b, s, :] = wv[b, rep_ids[b,s], :] * rep_mask ----
    g.x *= rm; g.y *= rm; g.z *= rm; g.w *= rm;
    __stcs(&out4[((long long)b * (2 * PS) + s) * D4 + t], g);

    // ---- optional mask tail (if harness flattens the tuple's second output) ----
    const long long n_vec = (long long)PB * 2 * PS * PD;
    if (out_size > n_vec && t == 0) {
        long long mbase = n_vec + (long long)b * (2 * PS);
        if (mbase + s < out_size)       out[mbase + s]       = rm;
        if (mbase + PS + s < out_size)  out[mbase + PS + s]  = lm;
    }
}

extern "C" void kernel_launch(void* const* d_in, const int* in_sizes, int n_in,
                              void* d_out, int out_size) {
    const float* wv       = (const float*)d_in[0];
    const int*   rep_ids  = (const int*)d_in[1];
    const int*   rep_mask = (const int*)d_in[2];
    const int*   lengths  = (const int*)d_in[3];
    const int*   len_mask = (const int*)d_in[4];
    float* out = (float*)d_out;

    pooling_kernel<<<NBLOCKS, NTHREADS>>>(wv, rep_ids, rep_mask, lengths,
                                          len_mask, out, (long long)out_size);
}